// round 1
// baseline (speedup 1.0000x reference)
#include <cuda_runtime.h>

#define B_  8
#define S_  4096
#define D_  256
#define DV_ 256
#define EPS_ 1e-6f

// Scratch for per-batch KV = (relu(K)+eps)^T @ V : [B, D, DV] fp32 = 2 MB
__device__ float g_KV[B_ * D_ * DV_];

// ---------------------------------------------------------------------------
// Kernel 1: KV[b,d,v] = sum_s (relu(K[b,s,d])+eps) * V[b,s,v]
// Grid: (DV/64, D/64, B) = (4,4,8) = 128 blocks, 256 threads.
// 64x64 output tile per block, 4x4 register tile per thread, s-chunks of 32.
// ---------------------------------------------------------------------------
__global__ __launch_bounds__(256, 1)
void kv_kernel(const float* __restrict__ K, const float* __restrict__ V) {
    __shared__ float Ks[32][68];  // [s][d], +4 pad
    __shared__ float Vs[32][68];  // [s][v], +4 pad

    const int b  = blockIdx.z;
    const int d0 = blockIdx.y * 64;
    const int v0 = blockIdx.x * 64;
    const int t  = threadIdx.x;
    const int tx = t & 15;        // v direction
    const int ty = t >> 4;        // d direction

    const float* __restrict__ Kb = K + (size_t)b * S_ * D_;
    const float* __restrict__ Vb = V + (size_t)b * S_ * DV_;

    float acc[4][4];
#pragma unroll
    for (int i = 0; i < 4; i++)
#pragma unroll
        for (int j = 0; j < 4; j++) acc[i][j] = 0.0f;

    for (int sc = 0; sc < S_; sc += 32) {
        // Load 32x64 K tile (relu+eps fused) and 32x64 V tile, float4 coalesced.
#pragma unroll
        for (int i = 0; i < 2; i++) {
            int idx = t + i * 256;          // 0..511
            int row = idx >> 4;             // 0..31
            int col = (idx & 15) * 4;       // 0..60
            float4 k4 = *(const float4*)(Kb + (size_t)(sc + row) * D_ + d0 + col);
            k4.x = fmaxf(k4.x, 0.0f) + EPS_;
            k4.y = fmaxf(k4.y, 0.0f) + EPS_;
            k4.z = fmaxf(k4.z, 0.0f) + EPS_;
            k4.w = fmaxf(k4.w, 0.0f) + EPS_;
            *(float4*)&Ks[row][col] = k4;
            float4 v4 = *(const float4*)(Vb + (size_t)(sc + row) * DV_ + v0 + col);
            *(float4*)&Vs[row][col] = v4;
        }
        __syncthreads();

#pragma unroll
        for (int s = 0; s < 32; s++) {
            float4 a4 = *(const float4*)&Ks[s][ty * 4];
            float4 b4 = *(const float4*)&Vs[s][tx * 4];
            float a[4] = {a4.x, a4.y, a4.z, a4.w};
            float bb[4] = {b4.x, b4.y, b4.z, b4.w};
#pragma unroll
            for (int i = 0; i < 4; i++)
#pragma unroll
                for (int j = 0; j < 4; j++)
                    acc[i][j] = fmaf(a[i], bb[j], acc[i][j]);
        }
        __syncthreads();
    }

    float* __restrict__ out = g_KV + (size_t)b * D_ * DV_;
#pragma unroll
    for (int i = 0; i < 4; i++) {
        float4 o = make_float4(acc[i][0], acc[i][1], acc[i][2], acc[i][3]);
        *(float4*)&out[(size_t)(d0 + ty * 4 + i) * DV_ + v0 + tx * 4] = o;
    }
}

// ---------------------------------------------------------------------------
// Kernel 2: out[b,q,v] = sum_d (relu(Q[b,q,d])+eps) * KV[b,d,v]
// Grid: (DV/64, S/64, B) = (4,64,8) = 2048 blocks, 256 threads.
// 64x64 output tile, d-chunks of 32. Q tile stored transposed [d][q] in smem.
// ---------------------------------------------------------------------------
__global__ __launch_bounds__(256, 1)
void out_kernel(const float* __restrict__ Q, float* __restrict__ O) {
    __shared__ float Qs[32][68];   // [d][q], +4 pad (float4-aligned rows)
    __shared__ float KVs[32][68];  // [d][v], +4 pad

    const int b  = blockIdx.z;
    const int q0 = blockIdx.y * 64;
    const int v0 = blockIdx.x * 64;
    const int t  = threadIdx.x;
    const int tx = t & 15;        // v direction
    const int ty = t >> 4;        // q direction

    const float* __restrict__ Qb  = Q + (size_t)b * S_ * D_;
    const float* __restrict__ KVb = g_KV + (size_t)b * D_ * DV_;

    float acc[4][4];
#pragma unroll
    for (int i = 0; i < 4; i++)
#pragma unroll
        for (int j = 0; j < 4; j++) acc[i][j] = 0.0f;

    for (int dc = 0; dc < D_; dc += 32) {
        // Q tile: 64 q-rows x 32 d-cols, loaded coalesced, stored transposed.
#pragma unroll
        for (int i = 0; i < 2; i++) {
            int idx = t + i * 256;          // 0..511
            int row = idx >> 3;             // q: 0..63
            int col = (idx & 7) * 4;        // d: 0..28
            float4 q4 = *(const float4*)(Qb + (size_t)(q0 + row) * D_ + dc + col);
            Qs[col + 0][row] = fmaxf(q4.x, 0.0f) + EPS_;
            Qs[col + 1][row] = fmaxf(q4.y, 0.0f) + EPS_;
            Qs[col + 2][row] = fmaxf(q4.z, 0.0f) + EPS_;
            Qs[col + 3][row] = fmaxf(q4.w, 0.0f) + EPS_;
        }
        // KV tile: 32 d-rows x 64 v-cols.
#pragma unroll
        for (int i = 0; i < 2; i++) {
            int idx = t + i * 256;
            int row = idx >> 4;             // d: 0..31
            int col = (idx & 15) * 4;       // v: 0..60
            float4 c4 = *(const float4*)(KVb + (size_t)(dc + row) * DV_ + v0 + col);
            *(float4*)&KVs[row][col] = c4;
        }
        __syncthreads();

#pragma unroll
        for (int d = 0; d < 32; d++) {
            float4 a4 = *(const float4*)&Qs[d][ty * 4];
            float4 b4 = *(const float4*)&KVs[d][tx * 4];
            float a[4] = {a4.x, a4.y, a4.z, a4.w};
            float bb[4] = {b4.x, b4.y, b4.z, b4.w};
#pragma unroll
            for (int i = 0; i < 4; i++)
#pragma unroll
                for (int j = 0; j < 4; j++)
                    acc[i][j] = fmaf(a[i], bb[j], acc[i][j]);
        }
        __syncthreads();
    }

    float* __restrict__ Ob = O + (size_t)b * S_ * DV_;
#pragma unroll
    for (int i = 0; i < 4; i++) {
        float4 o = make_float4(acc[i][0], acc[i][1], acc[i][2], acc[i][3]);
        *(float4*)&Ob[(size_t)(q0 + ty * 4 + i) * DV_ + v0 + tx * 4] = o;
    }
}

extern "C" void kernel_launch(void* const* d_in, const int* in_sizes, int n_in,
                              void* d_out, int out_size) {
    const float* Q = (const float*)d_in[0];
    const float* K = (const float*)d_in[1];
    const float* V = (const float*)d_in[2];
    float* O = (float*)d_out;

    dim3 blk(256);
    dim3 g1(DV_ / 64, D_ / 64, B_);   // 4,4,8
    dim3 g2(DV_ / 64, S_ / 64, B_);   // 4,64,8

    kv_kernel<<<g1, blk>>>(K, V);
    out_kernel<<<g2, blk>>>(Q, O);
}

// round 3
// speedup vs baseline: 1.9747x; 1.9747x over previous
#include <cuda_runtime.h>
#include <cuda_bf16.h>
#include <cstdint>

#define B_  8
#define S_  4096
#define D_  256
#define DV_ 256
#define EPS_ 1e-6f

#define SPLITS 16
#define S_PER  (S_ / SPLITS)     // 256
#define KC     32                // k-chunk (bf16 elems)
#define LDSB   80                // smem row stride in bytes (40 bf16, conflict-free)
#define TILEB  (128 * LDSB)      // 10240 bytes per tile

__device__ float g_part[SPLITS * B_ * DV_ * D_];  // 32 MB split-S partials
__device__ float g_KVT[B_ * DV_ * D_];            // KV^T [b][v][d]

// ---------------------------------------------------------------------------
__device__ __forceinline__ uint32_t smem_to_u32(const void* p) {
    uint32_t a;
    asm("{ .reg .u64 t; cvta.to.shared.u64 t, %1; cvt.u32.u64 %0, t; }"
        : "=r"(a) : "l"(p));
    return a;
}
__device__ __forceinline__ void ldmx4(uint32_t* r, uint32_t addr) {
    asm volatile("ldmatrix.sync.aligned.m8n8.x4.shared.b16 {%0,%1,%2,%3}, [%4];"
        : "=r"(r[0]), "=r"(r[1]), "=r"(r[2]), "=r"(r[3]) : "r"(addr));
}
__device__ __forceinline__ void mma16816(float* c, const uint32_t* a, const uint32_t* b) {
    asm volatile(
        "mma.sync.aligned.m16n8k16.row.col.f32.bf16.bf16.f32 "
        "{%0,%1,%2,%3}, {%4,%5,%6,%7}, {%8,%9}, {%0,%1,%2,%3};"
        : "+f"(c[0]), "+f"(c[1]), "+f"(c[2]), "+f"(c[3])
        : "r"(a[0]), "r"(a[1]), "r"(a[2]), "r"(a[3]), "r"(b[0]), "r"(b[1]));
}

// float -> (bf16 hi, bf16 lo) packed pairs
__device__ __forceinline__ void split2(float x0, float x1, uint32_t& h, uint32_t& l) {
    __nv_bfloat16 h0 = __float2bfloat16(x0), h1 = __float2bfloat16(x1);
    float r0 = x0 - __bfloat162float(h0), r1 = x1 - __bfloat162float(h1);
    __nv_bfloat16 l0 = __float2bfloat16(r0), l1 = __float2bfloat16(r1);
    h = ((uint32_t)__bfloat16_as_ushort(h1) << 16) | (uint32_t)__bfloat16_as_ushort(h0);
    l = ((uint32_t)__bfloat16_as_ushort(l1) << 16) | (uint32_t)__bfloat16_as_ushort(l0);
}

// One 128x128x32 chunk of split-precision MMA for this warp.
// Smem layout per tile: [row][k], 80B row stride, k contiguous (bf16).
__device__ __forceinline__ void warp_chunk_mma(
    uint32_t aHi, uint32_t aLo, uint32_t bHi, uint32_t bLo,
    int lane, int wm, int wn, float (*acc)[4])   // acc[mi*8+ni][4]
{
#pragma unroll
    for (int ks = 0; ks < 2; ks++) {
        // A fragments (m16k16): row = wm + mi*16 + (lane&15), koff = (lane>>4)*8 + ks*16
        uint32_t aoff = (uint32_t)((wm + (lane & 15)) * LDSB
                                   + ((lane >> 4) * 8 + ks * 16) * 2);
        uint32_t ah[2][4], al[2][4];
#pragma unroll
        for (int mi = 0; mi < 2; mi++) {
            ldmx4(ah[mi], aHi + aoff + mi * 16 * LDSB);
            ldmx4(al[mi], aLo + aoff + mi * 16 * LDSB);
        }
        // B fragments (k16n8), n-major storage: pairs of n-tiles per ldmatrix.x4
        uint32_t boff = (uint32_t)((wn + (lane & 7) + ((lane >> 4) << 3)) * LDSB
                                   + (((lane >> 3) & 1) * 8 + ks * 16) * 2);
        uint32_t bh[8][2], bl[8][2];
#pragma unroll
        for (int pi = 0; pi < 4; pi++) {
            uint32_t r4[4];
            ldmx4(r4, bHi + boff + pi * 16 * LDSB);
            bh[2*pi][0] = r4[0]; bh[2*pi][1] = r4[1];
            bh[2*pi+1][0] = r4[2]; bh[2*pi+1][1] = r4[3];
            ldmx4(r4, bLo + boff + pi * 16 * LDSB);
            bl[2*pi][0] = r4[0]; bl[2*pi][1] = r4[1];
            bl[2*pi+1][0] = r4[2]; bl[2*pi+1][1] = r4[3];
        }
#pragma unroll
        for (int mi = 0; mi < 2; mi++)
#pragma unroll
            for (int ni = 0; ni < 8; ni++) {
                float* c = acc[mi * 8 + ni];
                mma16816(c, ah[mi], bh[ni]);
                mma16816(c, ah[mi], bl[ni]);
                mma16816(c, al[mi], bh[ni]);
            }
    }
}

// ---------------------------------------------------------------------------
// Kernel 1: partial KV^T[v,d] = sum_{s in split} V[s,v] * (relu(K[s,d])+eps)
// M=v (A=V^T), N=d (B=K_^T), K-dim=s. Grid (4, SPLITS, B) = 512 CTAs.
// ---------------------------------------------------------------------------
__global__ __launch_bounds__(256, 1)
void kv_kernel(const float* __restrict__ K, const float* __restrict__ V) {
    __shared__ __align__(16) char smem[4 * TILEB];
    char* pAhi = smem;           char* pAlo = smem + TILEB;
    char* pBhi = smem + 2*TILEB; char* pBlo = smem + 3*TILEB;
    const uint32_t sb = smem_to_u32(smem);
    const uint32_t aHi = sb, aLo = sb + TILEB, bHi = sb + 2*TILEB, bLo = sb + 3*TILEB;

    const int t = threadIdx.x, lane = t & 31, wid = t >> 5;
    const int wm = (wid & 3) * 32, wn = (wid >> 2) * 64;
    const int b = blockIdx.z, p = blockIdx.y;
    const int v0 = (blockIdx.x & 1) * 128, d0 = (blockIdx.x >> 1) * 128;

    const float* __restrict__ Vb = V + (size_t)b * S_ * DV_;
    const float* __restrict__ Kb = K + (size_t)b * S_ * D_;

    float acc[16][4];
#pragma unroll
    for (int i = 0; i < 16; i++)
#pragma unroll
        for (int j = 0; j < 4; j++) acc[i][j] = 0.0f;

    for (int c = 0; c < S_PER / KC; c++) {   // 8 chunks
        const int s_c = p * S_PER + c * KC;
        __syncthreads();
#pragma unroll
        for (int i = 0; i < 4; i++) {
            int idx = t + i * 256;       // 0..1023
            int r   = idx & 127;         // lanes consecutive -> coalesced LDG
            int sg  = idx >> 7;          // 0..7, s-group of 4
            int s0  = s_c + sg * 4;
            uint32_t h01, l01, h23, l23;
            // A = V^T: row v=r, k=s
            float a0 = Vb[(size_t)(s0 + 0) * DV_ + v0 + r];
            float a1 = Vb[(size_t)(s0 + 1) * DV_ + v0 + r];
            float a2 = Vb[(size_t)(s0 + 2) * DV_ + v0 + r];
            float a3 = Vb[(size_t)(s0 + 3) * DV_ + v0 + r];
            split2(a0, a1, h01, l01); split2(a2, a3, h23, l23);
            *(uint2*)(pAhi + r * LDSB + sg * 8) = make_uint2(h01, h23);
            *(uint2*)(pAlo + r * LDSB + sg * 8) = make_uint2(l01, l23);
            // B = (relu(K)+eps)^T: row d=r, k=s
            float b0 = fmaxf(Kb[(size_t)(s0 + 0) * D_ + d0 + r], 0.f) + EPS_;
            float b1 = fmaxf(Kb[(size_t)(s0 + 1) * D_ + d0 + r], 0.f) + EPS_;
            float b2 = fmaxf(Kb[(size_t)(s0 + 2) * D_ + d0 + r], 0.f) + EPS_;
            float b3 = fmaxf(Kb[(size_t)(s0 + 3) * D_ + d0 + r], 0.f) + EPS_;
            split2(b0, b1, h01, l01); split2(b2, b3, h23, l23);
            *(uint2*)(pBhi + r * LDSB + sg * 8) = make_uint2(h01, h23);
            *(uint2*)(pBlo + r * LDSB + sg * 8) = make_uint2(l01, l23);
        }
        __syncthreads();
        warp_chunk_mma(aHi, aLo, bHi, bLo, lane, wm, wn, acc);
    }

    // Epilogue: C[v,d] -> g_part
    float* dst = g_part + (size_t)(p * B_ + b) * DV_ * D_;
    const int rr = lane >> 2, cc = (lane & 3) * 2;
#pragma unroll
    for (int mi = 0; mi < 2; mi++)
#pragma unroll
        for (int ni = 0; ni < 8; ni++) {
            int row = v0 + wm + mi * 16 + rr;
            int col = d0 + wn + ni * 8 + cc;
            float* cp = acc[mi * 8 + ni];
            *(float2*)(dst + (size_t)row * D_ + col)       = make_float2(cp[0], cp[1]);
            *(float2*)(dst + (size_t)(row + 8) * D_ + col) = make_float2(cp[2], cp[3]);
        }
}

// ---------------------------------------------------------------------------
// Kernel 2: g_KVT = sum over SPLITS partials
// ---------------------------------------------------------------------------
__global__ __launch_bounds__(256)
void reduce_kernel() {
    const int i = blockIdx.x * 256 + threadIdx.x;  // float4 idx, 131072 total
    const size_t stride4 = (size_t)B_ * DV_ * D_ / 4;
    float4 acc = make_float4(0.f, 0.f, 0.f, 0.f);
#pragma unroll
    for (int p = 0; p < SPLITS; p++) {
        float4 v = ((const float4*)g_part)[p * stride4 + i];
        acc.x += v.x; acc.y += v.y; acc.z += v.z; acc.w += v.w;
    }
    ((float4*)g_KVT)[i] = acc;
}

// ---------------------------------------------------------------------------
// Kernel 3: out[q,v] = (relu(Q)+eps)[q,d] @ KVT[v,d]^T  (both k=d contiguous)
// Grid (2, 32, B) = 512 CTAs.
// ---------------------------------------------------------------------------
__global__ __launch_bounds__(256, 1)
void out_kernel(const float* __restrict__ Q, float* __restrict__ O) {
    __shared__ __align__(16) char smem[4 * TILEB];
    char* pAhi = smem;           char* pAlo = smem + TILEB;
    char* pBhi = smem + 2*TILEB; char* pBlo = smem + 3*TILEB;
    const uint32_t sb = smem_to_u32(smem);
    const uint32_t aHi = sb, aLo = sb + TILEB, bHi = sb + 2*TILEB, bLo = sb + 3*TILEB;

    const int t = threadIdx.x, lane = t & 31, wid = t >> 5;
    const int wm = (wid & 3) * 32, wn = (wid >> 2) * 64;
    const int b = blockIdx.z;
    const int q0 = blockIdx.y * 128, v0 = blockIdx.x * 128;

    const float* __restrict__ Qb = Q + (size_t)b * S_ * D_;
    const float* __restrict__ Cb = g_KVT + (size_t)b * DV_ * D_;

    float acc[16][4];
#pragma unroll
    for (int i = 0; i < 16; i++)
#pragma unroll
        for (int j = 0; j < 4; j++) acc[i][j] = 0.0f;

    for (int c = 0; c < D_ / KC; c++) {      // 8 chunks
        const int dc = c * KC;
        __syncthreads();
#pragma unroll
        for (int i = 0; i < 4; i++) {
            int idx = t + i * 256;       // 0..1023
            int row = idx >> 3;          // 0..127
            int f4  = idx & 7;           // 0..7
            uint32_t h01, l01, h23, l23;
            // A = relu(Q)+eps  [q][d]
            float4 q4 = *(const float4*)(Qb + (size_t)(q0 + row) * D_ + dc + f4 * 4);
            q4.x = fmaxf(q4.x, 0.f) + EPS_;
            q4.y = fmaxf(q4.y, 0.f) + EPS_;
            q4.z = fmaxf(q4.z, 0.f) + EPS_;
            q4.w = fmaxf(q4.w, 0.f) + EPS_;
            split2(q4.x, q4.y, h01, l01); split2(q4.z, q4.w, h23, l23);
            *(uint2*)(pAhi + row * LDSB + f4 * 8) = make_uint2(h01, h23);
            *(uint2*)(pAlo + row * LDSB + f4 * 8) = make_uint2(l01, l23);
            // B = KVT  [v][d]
            float4 c4 = *(const float4*)(Cb + (size_t)(v0 + row) * D_ + dc + f4 * 4);
            split2(c4.x, c4.y, h01, l01); split2(c4.z, c4.w, h23, l23);
            *(uint2*)(pBhi + row * LDSB + f4 * 8) = make_uint2(h01, h23);
            *(uint2*)(pBlo + row * LDSB + f4 * 8) = make_uint2(l01, l23);
        }
        __syncthreads();
        warp_chunk_mma(aHi, aLo, bHi, bLo, lane, wm, wn, acc);
    }

    // Epilogue: C[q,v] -> O
    float* dst = O + (size_t)b * S_ * DV_;
    const int rr = lane >> 2, cc = (lane & 3) * 2;
#pragma unroll
    for (int mi = 0; mi < 2; mi++)
#pragma unroll
        for (int ni = 0; ni < 8; ni++) {
            int row = q0 + wm + mi * 16 + rr;
            int col = v0 + wn + ni * 8 + cc;
            float* cp = acc[mi * 8 + ni];
            *(float2*)(dst + (size_t)row * DV_ + col)       = make_float2(cp[0], cp[1]);
            *(float2*)(dst + (size_t)(row + 8) * DV_ + col) = make_float2(cp[2], cp[3]);
        }
}

extern "C" void kernel_launch(void* const* d_in, const int* in_sizes, int n_in,
                              void* d_out, int out_size) {
    const float* Q = (const float*)d_in[0];
    const float* K = (const float*)d_in[1];
    const float* V = (const float*)d_in[2];
    float* O = (float*)d_out;

    kv_kernel<<<dim3(4, SPLITS, B_), 256>>>(K, V);
    reduce_kernel<<<512, 256>>>();
    out_kernel<<<dim3(2, 32, B_), 256>>>(Q, O);
}

// round 4
// speedup vs baseline: 2.3439x; 1.1870x over previous
#include <cuda_runtime.h>
#include <cuda_bf16.h>
#include <cstdint>

#define B_  8
#define S_  4096
#define D_  256
#define DV_ 256
#define EPS_ 1e-6f

#define SPLITS 16
#define S_PER  (S_ / SPLITS)     // 256
#define KC     32                // k-chunk (bf16 elems)
#define LDSB   80                // smem row stride bytes (40 bf16, conflict-free)
#define TILEB  (128 * LDSB)      // 10240 bytes per tile
#define BUFB   (4 * TILEB)       // A hi/lo + B hi/lo
#define SMEM_TOTAL (2 * BUFB)    // 81920 bytes, double-buffered

__device__ float g_part[SPLITS * B_ * DV_ * D_];  // 32 MB split-S partials
__device__ float g_KVT[B_ * DV_ * D_];            // KV^T [b][v][d]

// ---------------------------------------------------------------------------
__device__ __forceinline__ uint32_t smem_to_u32(const void* p) {
    uint32_t a;
    asm("{ .reg .u64 t; cvta.to.shared.u64 t, %1; cvt.u32.u64 %0, t; }"
        : "=r"(a) : "l"(p));
    return a;
}
__device__ __forceinline__ void ldmx4(uint32_t* r, uint32_t addr) {
    asm volatile("ldmatrix.sync.aligned.m8n8.x4.shared.b16 {%0,%1,%2,%3}, [%4];"
        : "=r"(r[0]), "=r"(r[1]), "=r"(r[2]), "=r"(r[3]) : "r"(addr));
}
__device__ __forceinline__ void mma16816(float* c, const uint32_t* a, const uint32_t* b) {
    asm volatile(
        "mma.sync.aligned.m16n8k16.row.col.f32.bf16.bf16.f32 "
        "{%0,%1,%2,%3}, {%4,%5,%6,%7}, {%8,%9}, {%0,%1,%2,%3};"
        : "+f"(c[0]), "+f"(c[1]), "+f"(c[2]), "+f"(c[3])
        : "r"(a[0]), "r"(a[1]), "r"(a[2]), "r"(a[3]), "r"(b[0]), "r"(b[1]));
}

// float -> (bf16 hi, bf16 lo) packed pairs
__device__ __forceinline__ void split2(float x0, float x1, uint32_t& h, uint32_t& l) {
    __nv_bfloat16 h0 = __float2bfloat16(x0), h1 = __float2bfloat16(x1);
    float r0 = x0 - __bfloat162float(h0), r1 = x1 - __bfloat162float(h1);
    __nv_bfloat16 l0 = __float2bfloat16(r0), l1 = __float2bfloat16(r1);
    h = ((uint32_t)__bfloat16_as_ushort(h1) << 16) | (uint32_t)__bfloat16_as_ushort(h0);
    l = ((uint32_t)__bfloat16_as_ushort(l1) << 16) | (uint32_t)__bfloat16_as_ushort(l0);
}

// One 128x128x32 chunk of split-precision MMA for this warp.
// Tile layout: [row][k], LDSB row stride, k contiguous (bf16).
__device__ __forceinline__ void warp_chunk_mma(
    uint32_t aHi, uint32_t aLo, uint32_t bHi, uint32_t bLo,
    int lane, int wm, int wn, float (*acc)[4])   // acc[mi*8+ni][4]
{
#pragma unroll
    for (int ks = 0; ks < 2; ks++) {
        uint32_t aoff = (uint32_t)((wm + (lane & 15)) * LDSB
                                   + ((lane >> 4) * 8 + ks * 16) * 2);
        uint32_t ah[2][4], al[2][4];
#pragma unroll
        for (int mi = 0; mi < 2; mi++) {
            ldmx4(ah[mi], aHi + aoff + mi * 16 * LDSB);
            ldmx4(al[mi], aLo + aoff + mi * 16 * LDSB);
        }
        uint32_t boff = (uint32_t)((wn + (lane & 7) + ((lane >> 4) << 3)) * LDSB
                                   + (((lane >> 3) & 1) * 8 + ks * 16) * 2);
        uint32_t bh[8][2], bl[8][2];
#pragma unroll
        for (int pi = 0; pi < 4; pi++) {
            uint32_t r4[4];
            ldmx4(r4, bHi + boff + pi * 16 * LDSB);
            bh[2*pi][0] = r4[0]; bh[2*pi][1] = r4[1];
            bh[2*pi+1][0] = r4[2]; bh[2*pi+1][1] = r4[3];
            ldmx4(r4, bLo + boff + pi * 16 * LDSB);
            bl[2*pi][0] = r4[0]; bl[2*pi][1] = r4[1];
            bl[2*pi+1][0] = r4[2]; bl[2*pi+1][1] = r4[3];
        }
#pragma unroll
        for (int mi = 0; mi < 2; mi++)
#pragma unroll
            for (int ni = 0; ni < 8; ni++) {
                float* c = acc[mi * 8 + ni];
                mma16816(c, ah[mi], bh[ni]);
                mma16816(c, ah[mi], bl[ni]);
                mma16816(c, al[mi], bh[ni]);
            }
    }
}

// ---------------------------------------------------------------------------
// Kernel 1: partial KV^T[v,d] = sum_{s in split} V[s,v] * (relu(K[s,d])+eps)
// Double-buffered software pipeline: LDG(c+1) overlaps MMA(c).
// ---------------------------------------------------------------------------
__global__ __launch_bounds__(256, 1)
void kv_kernel(const float* __restrict__ K, const float* __restrict__ V) {
    extern __shared__ __align__(16) char smem[];
    const uint32_t sb = smem_to_u32(smem);

    const int t = threadIdx.x, lane = t & 31, wid = t >> 5;
    const int wm = (wid & 3) * 32, wn = (wid >> 2) * 64;
    const int b = blockIdx.z, p = blockIdx.y;
    const int v0 = (blockIdx.x & 1) * 128, d0 = (blockIdx.x >> 1) * 128;

    const float* __restrict__ Vb = V + (size_t)b * S_ * DV_;
    const float* __restrict__ Kb = K + (size_t)b * S_ * D_;

    float acc[16][4];
#pragma unroll
    for (int i = 0; i < 16; i++)
#pragma unroll
        for (int j = 0; j < 4; j++) acc[i][j] = 0.0f;

    float ra[16], rb[16];
    const int r_  = t & 127;          // row handled by this thread (same all i)
    const int sgB = (t >> 7) * 4;     // base s-group (0 or 4)

    // prologue: load chunk 0
    {
        const int s_c = p * S_PER;
#pragma unroll
        for (int i = 0; i < 4; i++) {
            int sg = sgB + ((i & 1) << 1) + (i >> 1);   // any coverage of 0..3 offsets
            // simpler: sg = sgB + i
            sg = sgB + i;
            int s0 = s_c + sg * 4;
#pragma unroll
            for (int j = 0; j < 4; j++) {
                ra[i * 4 + j] = Vb[(size_t)(s0 + j) * DV_ + v0 + r_];
                rb[i * 4 + j] = fmaxf(Kb[(size_t)(s0 + j) * D_ + d0 + r_], 0.f) + EPS_;
            }
        }
    }

    const int NC = S_PER / KC;   // 8
    for (int c = 0; c < NC; c++) {
        char* base = smem + (size_t)(c & 1) * BUFB;
        char* pAhi = base;            char* pAlo = base + TILEB;
        char* pBhi = base + 2*TILEB;  char* pBlo = base + 3*TILEB;
        // store current regs -> smem tiles
#pragma unroll
        for (int i = 0; i < 4; i++) {
            int sg = sgB + i;
            uint32_t h01, l01, h23, l23;
            split2(ra[i*4+0], ra[i*4+1], h01, l01);
            split2(ra[i*4+2], ra[i*4+3], h23, l23);
            *(uint2*)(pAhi + r_ * LDSB + sg * 8) = make_uint2(h01, h23);
            *(uint2*)(pAlo + r_ * LDSB + sg * 8) = make_uint2(l01, l23);
            split2(rb[i*4+0], rb[i*4+1], h01, l01);
            split2(rb[i*4+2], rb[i*4+3], h23, l23);
            *(uint2*)(pBhi + r_ * LDSB + sg * 8) = make_uint2(h01, h23);
            *(uint2*)(pBlo + r_ * LDSB + sg * 8) = make_uint2(l01, l23);
        }
        __syncthreads();
        // prefetch next chunk (latency hides under MMA below)
        if (c + 1 < NC) {
            const int s_c = p * S_PER + (c + 1) * KC;
#pragma unroll
            for (int i = 0; i < 4; i++) {
                int s0 = s_c + (sgB + i) * 4;
#pragma unroll
                for (int j = 0; j < 4; j++) {
                    ra[i * 4 + j] = Vb[(size_t)(s0 + j) * DV_ + v0 + r_];
                    rb[i * 4 + j] = fmaxf(Kb[(size_t)(s0 + j) * D_ + d0 + r_], 0.f) + EPS_;
                }
            }
        }
        uint32_t ub = sb + (uint32_t)(c & 1) * BUFB;
        warp_chunk_mma(ub, ub + TILEB, ub + 2*TILEB, ub + 3*TILEB,
                       lane, wm, wn, acc);
    }

    // Epilogue: C[v,d] -> g_part
    float* dst = g_part + (size_t)(p * B_ + b) * DV_ * D_;
    const int rr = lane >> 2, cc = (lane & 3) * 2;
#pragma unroll
    for (int mi = 0; mi < 2; mi++)
#pragma unroll
        for (int ni = 0; ni < 8; ni++) {
            int row = v0 + wm + mi * 16 + rr;
            int col = d0 + wn + ni * 8 + cc;
            float* cp = acc[mi * 8 + ni];
            *(float2*)(dst + (size_t)row * D_ + col)       = make_float2(cp[0], cp[1]);
            *(float2*)(dst + (size_t)(row + 8) * D_ + col) = make_float2(cp[2], cp[3]);
        }
}

// ---------------------------------------------------------------------------
// Kernel 2: g_KVT = sum over SPLITS partials
// ---------------------------------------------------------------------------
__global__ __launch_bounds__(256)
void reduce_kernel() {
    const int i = blockIdx.x * 256 + threadIdx.x;  // float4 idx, 131072 total
    const size_t stride4 = (size_t)B_ * DV_ * D_ / 4;
    float4 acc = make_float4(0.f, 0.f, 0.f, 0.f);
#pragma unroll
    for (int p = 0; p < SPLITS; p++) {
        float4 v = ((const float4*)g_part)[p * stride4 + i];
        acc.x += v.x; acc.y += v.y; acc.z += v.z; acc.w += v.w;
    }
    ((float4*)g_KVT)[i] = acc;
}

// ---------------------------------------------------------------------------
// Kernel 3: out[q,v] = (relu(Q)+eps)[q,d] @ KVT[v,d]^T, pipelined like kv.
// ---------------------------------------------------------------------------
__global__ __launch_bounds__(256, 1)
void out_kernel(const float* __restrict__ Q, float* __restrict__ O) {
    extern __shared__ __align__(16) char smem[];
    const uint32_t sb = smem_to_u32(smem);

    const int t = threadIdx.x, lane = t & 31, wid = t >> 5;
    const int wm = (wid & 3) * 32, wn = (wid >> 2) * 64;
    const int b = blockIdx.z;
    const int q0 = blockIdx.y * 128, v0 = blockIdx.x * 128;

    const float* __restrict__ Qb = Q + (size_t)b * S_ * D_;
    const float* __restrict__ Cb = g_KVT + (size_t)b * DV_ * D_;

    float acc[16][4];
#pragma unroll
    for (int i = 0; i < 16; i++)
#pragma unroll
        for (int j = 0; j < 4; j++) acc[i][j] = 0.0f;

    // this thread's 4 (row, f4) slots: row = idx>>3, f4 = idx&7, idx = t + i*256
    float4 rq[4], rc[4];
#pragma unroll
    for (int i = 0; i < 4; i++) {
        int idx = t + i * 256;
        int row = idx >> 3, f4 = idx & 7;
        rq[i] = *(const float4*)(Qb + (size_t)(q0 + row) * D_ + f4 * 4);
        rc[i] = *(const float4*)(Cb + (size_t)(v0 + row) * D_ + f4 * 4);
    }

    const int NC = D_ / KC;   // 8
    for (int c = 0; c < NC; c++) {
        char* base = smem + (size_t)(c & 1) * BUFB;
        char* pAhi = base;            char* pAlo = base + TILEB;
        char* pBhi = base + 2*TILEB;  char* pBlo = base + 3*TILEB;
#pragma unroll
        for (int i = 0; i < 4; i++) {
            int idx = t + i * 256;
            int row = idx >> 3, f4 = idx & 7;
            float4 q4 = rq[i];
            q4.x = fmaxf(q4.x, 0.f) + EPS_;
            q4.y = fmaxf(q4.y, 0.f) + EPS_;
            q4.z = fmaxf(q4.z, 0.f) + EPS_;
            q4.w = fmaxf(q4.w, 0.f) + EPS_;
            uint32_t h01, l01, h23, l23;
            split2(q4.x, q4.y, h01, l01); split2(q4.z, q4.w, h23, l23);
            *(uint2*)(pAhi + row * LDSB + f4 * 8) = make_uint2(h01, h23);
            *(uint2*)(pAlo + row * LDSB + f4 * 8) = make_uint2(l01, l23);
            float4 c4 = rc[i];
            split2(c4.x, c4.y, h01, l01); split2(c4.z, c4.w, h23, l23);
            *(uint2*)(pBhi + row * LDSB + f4 * 8) = make_uint2(h01, h23);
            *(uint2*)(pBlo + row * LDSB + f4 * 8) = make_uint2(l01, l23);
        }
        __syncthreads();
        if (c + 1 < NC) {
            const int dc = (c + 1) * KC;
#pragma unroll
            for (int i = 0; i < 4; i++) {
                int idx = t + i * 256;
                int row = idx >> 3, f4 = idx & 7;
                rq[i] = *(const float4*)(Qb + (size_t)(q0 + row) * D_ + dc + f4 * 4);
                rc[i] = *(const float4*)(Cb + (size_t)(v0 + row) * D_ + dc + f4 * 4);
            }
        }
        uint32_t ub = sb + (uint32_t)(c & 1) * BUFB;
        warp_chunk_mma(ub, ub + TILEB, ub + 2*TILEB, ub + 3*TILEB,
                       lane, wm, wn, acc);
    }

    // Epilogue: C[q,v] -> O
    float* dst = O + (size_t)b * S_ * DV_;
    const int rr = lane >> 2, cc = (lane & 3) * 2;
#pragma unroll
    for (int mi = 0; mi < 2; mi++)
#pragma unroll
        for (int ni = 0; ni < 8; ni++) {
            int row = q0 + wm + mi * 16 + rr;
            int col = v0 + wn + ni * 8 + cc;
            float* cp = acc[mi * 8 + ni];
            *(float2*)(dst + (size_t)row * DV_ + col)       = make_float2(cp[0], cp[1]);
            *(float2*)(dst + (size_t)(row + 8) * DV_ + col) = make_float2(cp[2], cp[3]);
        }
}

extern "C" void kernel_launch(void* const* d_in, const int* in_sizes, int n_in,
                              void* d_out, int out_size) {
    const float* Q = (const float*)d_in[0];
    const float* K = (const float*)d_in[1];
    const float* V = (const float*)d_in[2];
    float* O = (float*)d_out;

    cudaFuncSetAttribute(kv_kernel,  cudaFuncAttributeMaxDynamicSharedMemorySize, SMEM_TOTAL);
    cudaFuncSetAttribute(out_kernel, cudaFuncAttributeMaxDynamicSharedMemorySize, SMEM_TOTAL);

    kv_kernel<<<dim3(4, SPLITS, B_), 256, SMEM_TOTAL>>>(K, V);
    reduce_kernel<<<512, 256>>>();
    out_kernel<<<dim3(2, 32, B_), 256, SMEM_TOTAL>>>(Q, O);
}

// round 5
// speedup vs baseline: 2.7112x; 1.1567x over previous
#include <cuda_runtime.h>
#include <cuda_bf16.h>
#include <cstdint>

#define B_  8
#define S_  4096
#define D_  256
#define DV_ 256
#define EPS_ 1e-6f

#define SPLITS 8
#define S_PER  (S_ / SPLITS)     // 512
#define KC     32                // k-chunk (bf16 elems)
#define LDSB   80                // smem row stride bytes (40 bf16, conflict-free)
#define TILEA  (128 * LDSB)      // 10240 B  (A: 128 rows)
#define TILEBN (64 * LDSB)       // 5120 B   (B: 64 rows)
#define BUFB   (2 * TILEA + 2 * TILEBN)  // 30720 B
#define SMEM_TOTAL (2 * BUFB)    // 61440 B double-buffered

#define OFF_AHI 0
#define OFF_ALO TILEA
#define OFF_BHI (2 * TILEA)
#define OFF_BLO (2 * TILEA + TILEBN)

__device__ float g_part[SPLITS * B_ * DV_ * D_];  // 16 MB split-S partials
__device__ float g_KVT[B_ * DV_ * D_];            // KV^T [b][v][d]

// ---------------------------------------------------------------------------
__device__ __forceinline__ uint32_t smem_to_u32(const void* p) {
    uint32_t a;
    asm("{ .reg .u64 t; cvta.to.shared.u64 t, %1; cvt.u32.u64 %0, t; }"
        : "=r"(a) : "l"(p));
    return a;
}
__device__ __forceinline__ void ldmx4(uint32_t* r, uint32_t addr) {
    asm volatile("ldmatrix.sync.aligned.m8n8.x4.shared.b16 {%0,%1,%2,%3}, [%4];"
        : "=r"(r[0]), "=r"(r[1]), "=r"(r[2]), "=r"(r[3]) : "r"(addr));
}
__device__ __forceinline__ void mma16816(float* c, const uint32_t* a, const uint32_t* b) {
    asm volatile(
        "mma.sync.aligned.m16n8k16.row.col.f32.bf16.bf16.f32 "
        "{%0,%1,%2,%3}, {%4,%5,%6,%7}, {%8,%9}, {%0,%1,%2,%3};"
        : "+f"(c[0]), "+f"(c[1]), "+f"(c[2]), "+f"(c[3])
        : "r"(a[0]), "r"(a[1]), "r"(a[2]), "r"(a[3]), "r"(b[0]), "r"(b[1]));
}

// float -> (bf16 hi, bf16 lo) packed pairs
__device__ __forceinline__ void split2(float x0, float x1, uint32_t& h, uint32_t& l) {
    __nv_bfloat16 h0 = __float2bfloat16(x0), h1 = __float2bfloat16(x1);
    float r0 = x0 - __bfloat162float(h0), r1 = x1 - __bfloat162float(h1);
    __nv_bfloat16 l0 = __float2bfloat16(r0), l1 = __float2bfloat16(r1);
    h = ((uint32_t)__bfloat16_as_ushort(h1) << 16) | (uint32_t)__bfloat16_as_ushort(h0);
    l = ((uint32_t)__bfloat16_as_ushort(l1) << 16) | (uint32_t)__bfloat16_as_ushort(l0);
}

// One 128x64x32 chunk for this warp (warp tile 32x32).
// acc[mi*4+ni][4], mi<2, ni<4.
__device__ __forceinline__ void warp_chunk_mma(
    uint32_t buf, int lane, int wm, int wn, float (*acc)[4])
{
    const uint32_t aHi = buf + OFF_AHI, aLo = buf + OFF_ALO;
    const uint32_t bHi = buf + OFF_BHI, bLo = buf + OFF_BLO;
#pragma unroll
    for (int ks = 0; ks < 2; ks++) {
        uint32_t aoff = (uint32_t)((wm + (lane & 15)) * LDSB
                                   + ((lane >> 4) * 8 + ks * 16) * 2);
        uint32_t ah[2][4], al[2][4];
#pragma unroll
        for (int mi = 0; mi < 2; mi++) {
            ldmx4(ah[mi], aHi + aoff + mi * 16 * LDSB);
            ldmx4(al[mi], aLo + aoff + mi * 16 * LDSB);
        }
        uint32_t boff = (uint32_t)((wn + (lane & 7) + ((lane >> 4) << 3)) * LDSB
                                   + (((lane >> 3) & 1) * 8 + ks * 16) * 2);
        uint32_t bh[4][2], bl[4][2];
#pragma unroll
        for (int pi = 0; pi < 2; pi++) {
            uint32_t r4[4];
            ldmx4(r4, bHi + boff + pi * 16 * LDSB);
            bh[2*pi][0] = r4[0]; bh[2*pi][1] = r4[1];
            bh[2*pi+1][0] = r4[2]; bh[2*pi+1][1] = r4[3];
            ldmx4(r4, bLo + boff + pi * 16 * LDSB);
            bl[2*pi][0] = r4[0]; bl[2*pi][1] = r4[1];
            bl[2*pi+1][0] = r4[2]; bl[2*pi+1][1] = r4[3];
        }
#pragma unroll
        for (int mi = 0; mi < 2; mi++)
#pragma unroll
            for (int ni = 0; ni < 4; ni++) {
                float* c = acc[mi * 4 + ni];
                mma16816(c, ah[mi], bh[ni]);
                mma16816(c, ah[mi], bl[ni]);
                mma16816(c, al[mi], bh[ni]);
            }
    }
}

// ---------------------------------------------------------------------------
// Kernel 1: partial KV^T[v,d] = sum_{s in split} V[s,v] * (relu(K[s,d])+eps)
// A = V^T (128 v-rows), B = K_^T (64 d-rows). Grid (8, SPLITS, B) = 512 CTAs.
// ---------------------------------------------------------------------------
__global__ __launch_bounds__(256, 2)
void kv_kernel(const float* __restrict__ K, const float* __restrict__ V) {
    extern __shared__ __align__(16) char smem[];
    const uint32_t sb = smem_to_u32(smem);

    const int t = threadIdx.x, lane = t & 31, wid = t >> 5;
    const int wm = (wid & 3) * 32, wn = (wid >> 2) * 32;
    const int b = blockIdx.z, p = blockIdx.y;
    const int v0 = (blockIdx.x & 1) * 128, d0 = (blockIdx.x >> 1) * 64;

    const float* __restrict__ Vb = V + (size_t)b * S_ * DV_;
    const float* __restrict__ Kb = K + (size_t)b * S_ * D_;

    float acc[8][4];
#pragma unroll
    for (int i = 0; i < 8; i++)
#pragma unroll
        for (int j = 0; j < 4; j++) acc[i][j] = 0.0f;

    float ra[16], rb[8];
    const int rA  = t & 127;          // A row (v)
    const int sgA = (t >> 7) * 4;     // A s-group base (4 groups)
    const int rB  = t & 63;           // B row (d)
    const int sgB = (t >> 6) * 2;     // B s-group base (2 groups)

    // prologue: chunk 0
    {
        const int s_c = p * S_PER;
#pragma unroll
        for (int i = 0; i < 4; i++) {
            int s0 = s_c + (sgA + i) * 4;
#pragma unroll
            for (int j = 0; j < 4; j++)
                ra[i * 4 + j] = Vb[(size_t)(s0 + j) * DV_ + v0 + rA];
        }
#pragma unroll
        for (int i = 0; i < 2; i++) {
            int s0 = s_c + (sgB + i) * 4;
#pragma unroll
            for (int j = 0; j < 4; j++)
                rb[i * 4 + j] = fmaxf(Kb[(size_t)(s0 + j) * D_ + d0 + rB], 0.f) + EPS_;
        }
    }

    const int NC = S_PER / KC;   // 16
    for (int c = 0; c < NC; c++) {
        char* base = smem + (size_t)(c & 1) * BUFB;
#pragma unroll
        for (int i = 0; i < 4; i++) {
            int sg = sgA + i;
            uint32_t h01, l01, h23, l23;
            split2(ra[i*4+0], ra[i*4+1], h01, l01);
            split2(ra[i*4+2], ra[i*4+3], h23, l23);
            *(uint2*)(base + OFF_AHI + rA * LDSB + sg * 8) = make_uint2(h01, h23);
            *(uint2*)(base + OFF_ALO + rA * LDSB + sg * 8) = make_uint2(l01, l23);
        }
#pragma unroll
        for (int i = 0; i < 2; i++) {
            int sg = sgB + i;
            uint32_t h01, l01, h23, l23;
            split2(rb[i*4+0], rb[i*4+1], h01, l01);
            split2(rb[i*4+2], rb[i*4+3], h23, l23);
            *(uint2*)(base + OFF_BHI + rB * LDSB + sg * 8) = make_uint2(h01, h23);
            *(uint2*)(base + OFF_BLO + rB * LDSB + sg * 8) = make_uint2(l01, l23);
        }
        __syncthreads();
        if (c + 1 < NC) {
            const int s_c = p * S_PER + (c + 1) * KC;
#pragma unroll
            for (int i = 0; i < 4; i++) {
                int s0 = s_c + (sgA + i) * 4;
#pragma unroll
                for (int j = 0; j < 4; j++)
                    ra[i * 4 + j] = Vb[(size_t)(s0 + j) * DV_ + v0 + rA];
            }
#pragma unroll
            for (int i = 0; i < 2; i++) {
                int s0 = s_c + (sgB + i) * 4;
#pragma unroll
                for (int j = 0; j < 4; j++)
                    rb[i * 4 + j] = fmaxf(Kb[(size_t)(s0 + j) * D_ + d0 + rB], 0.f) + EPS_;
            }
        }
        warp_chunk_mma(sb + (uint32_t)(c & 1) * BUFB, lane, wm, wn, acc);
    }

    // Epilogue: C[v,d] -> g_part
    float* dst = g_part + (size_t)(p * B_ + b) * DV_ * D_;
    const int rr = lane >> 2, cc = (lane & 3) * 2;
#pragma unroll
    for (int mi = 0; mi < 2; mi++)
#pragma unroll
        for (int ni = 0; ni < 4; ni++) {
            int row = v0 + wm + mi * 16 + rr;
            int col = d0 + wn + ni * 8 + cc;
            float* cp = acc[mi * 4 + ni];
            *(float2*)(dst + (size_t)row * D_ + col)       = make_float2(cp[0], cp[1]);
            *(float2*)(dst + (size_t)(row + 8) * D_ + col) = make_float2(cp[2], cp[3]);
        }
}

// ---------------------------------------------------------------------------
// Kernel 2: g_KVT = sum over SPLITS partials
// ---------------------------------------------------------------------------
__global__ __launch_bounds__(256)
void reduce_kernel() {
    const int i = blockIdx.x * 256 + threadIdx.x;  // float4 idx, 131072 total
    const size_t stride4 = (size_t)B_ * DV_ * D_ / 4;
    float4 acc = make_float4(0.f, 0.f, 0.f, 0.f);
#pragma unroll
    for (int p = 0; p < SPLITS; p++) {
        float4 v = ((const float4*)g_part)[p * stride4 + i];
        acc.x += v.x; acc.y += v.y; acc.z += v.z; acc.w += v.w;
    }
    ((float4*)g_KVT)[i] = acc;
}

// ---------------------------------------------------------------------------
// Kernel 3: out[q,v] = (relu(Q)+eps)[q,d] @ KVT[v,d]^T
// A = Q_ (128 q-rows), B = KVT (64 v-rows). Grid (4, 32, B) = 1024 CTAs.
// ---------------------------------------------------------------------------
__global__ __launch_bounds__(256, 2)
void out_kernel(const float* __restrict__ Q, float* __restrict__ O) {
    extern __shared__ __align__(16) char smem[];
    const uint32_t sb = smem_to_u32(smem);

    const int t = threadIdx.x, lane = t & 31, wid = t >> 5;
    const int wm = (wid & 3) * 32, wn = (wid >> 2) * 32;
    const int b = blockIdx.z;
    const int q0 = blockIdx.y * 128, v0 = blockIdx.x * 64;

    const float* __restrict__ Qb = Q + (size_t)b * S_ * D_;
    const float* __restrict__ Cb = g_KVT + (size_t)b * DV_ * D_;

    float acc[8][4];
#pragma unroll
    for (int i = 0; i < 8; i++)
#pragma unroll
        for (int j = 0; j < 4; j++) acc[i][j] = 0.0f;

    // A slots: idx = t + i*256, row = idx>>3 (0..127), f4 = idx&7  (i<4)
    // B slots: idx = t + i*256, row = idx>>3 (0..63),  f4 = idx&7  (i<2)
    float4 rq[4], rc[2];
#pragma unroll
    for (int i = 0; i < 4; i++) {
        int idx = t + i * 256;
        rq[i] = *(const float4*)(Qb + (size_t)(q0 + (idx >> 3)) * D_ + (idx & 7) * 4);
    }
#pragma unroll
    for (int i = 0; i < 2; i++) {
        int idx = t + i * 256;
        rc[i] = *(const float4*)(Cb + (size_t)(v0 + (idx >> 3)) * D_ + (idx & 7) * 4);
    }

    const int NC = D_ / KC;   // 8
    for (int c = 0; c < NC; c++) {
        char* base = smem + (size_t)(c & 1) * BUFB;
#pragma unroll
        for (int i = 0; i < 4; i++) {
            int idx = t + i * 256;
            int row = idx >> 3, f4 = idx & 7;
            float4 q4 = rq[i];
            q4.x = fmaxf(q4.x, 0.f) + EPS_;
            q4.y = fmaxf(q4.y, 0.f) + EPS_;
            q4.z = fmaxf(q4.z, 0.f) + EPS_;
            q4.w = fmaxf(q4.w, 0.f) + EPS_;
            uint32_t h01, l01, h23, l23;
            split2(q4.x, q4.y, h01, l01); split2(q4.z, q4.w, h23, l23);
            *(uint2*)(base + OFF_AHI + row * LDSB + f4 * 8) = make_uint2(h01, h23);
            *(uint2*)(base + OFF_ALO + row * LDSB + f4 * 8) = make_uint2(l01, l23);
        }
#pragma unroll
        for (int i = 0; i < 2; i++) {
            int idx = t + i * 256;
            int row = idx >> 3, f4 = idx & 7;
            uint32_t h01, l01, h23, l23;
            float4 c4 = rc[i];
            split2(c4.x, c4.y, h01, l01); split2(c4.z, c4.w, h23, l23);
            *(uint2*)(base + OFF_BHI + row * LDSB + f4 * 8) = make_uint2(h01, h23);
            *(uint2*)(base + OFF_BLO + row * LDSB + f4 * 8) = make_uint2(l01, l23);
        }
        __syncthreads();
        if (c + 1 < NC) {
            const int dc = (c + 1) * KC;
#pragma unroll
            for (int i = 0; i < 4; i++) {
                int idx = t + i * 256;
                rq[i] = *(const float4*)(Qb + (size_t)(q0 + (idx >> 3)) * D_ + dc + (idx & 7) * 4);
            }
#pragma unroll
            for (int i = 0; i < 2; i++) {
                int idx = t + i * 256;
                rc[i] = *(const float4*)(Cb + (size_t)(v0 + (idx >> 3)) * D_ + dc + (idx & 7) * 4);
            }
        }
        warp_chunk_mma(sb + (uint32_t)(c & 1) * BUFB, lane, wm, wn, acc);
    }

    // Epilogue: C[q,v] -> O
    float* dst = O + (size_t)b * S_ * DV_;
    const int rr = lane >> 2, cc = (lane & 3) * 2;
#pragma unroll
    for (int mi = 0; mi < 2; mi++)
#pragma unroll
        for (int ni = 0; ni < 4; ni++) {
            int row = q0 + wm + mi * 16 + rr;
            int col = v0 + wn + ni * 8 + cc;
            float* cp = acc[mi * 4 + ni];
            *(float2*)(dst + (size_t)row * DV_ + col)       = make_float2(cp[0], cp[1]);
            *(float2*)(dst + (size_t)(row + 8) * DV_ + col) = make_float2(cp[2], cp[3]);
        }
}

extern "C" void kernel_launch(void* const* d_in, const int* in_sizes, int n_in,
                              void* d_out, int out_size) {
    const float* Q = (const float*)d_in[0];
    const float* K = (const float*)d_in[1];
    const float* V = (const float*)d_in[2];
    float* O = (float*)d_out;

    cudaFuncSetAttribute(kv_kernel,  cudaFuncAttributeMaxDynamicSharedMemorySize, SMEM_TOTAL);
    cudaFuncSetAttribute(out_kernel, cudaFuncAttributeMaxDynamicSharedMemorySize, SMEM_TOTAL);

    kv_kernel<<<dim3(8, SPLITS, B_), 256, SMEM_TOTAL>>>(K, V);
    reduce_kernel<<<512, 256>>>();
    out_kernel<<<dim3(4, 32, B_), 256, SMEM_TOTAL>>>(Q, O);
}

// round 6
// speedup vs baseline: 2.7163x; 1.0019x over previous
#include <cuda_runtime.h>
#include <cuda_bf16.h>
#include <cstdint>

#define B_  8
#define S_  4096
#define D_  256
#define DV_ 256
#define EPS_ 1e-6f

#define SPLITS 8
#define S_PER  (S_ / SPLITS)     // 512
#define KC     32                // k-chunk (bf16 elems)
#define LDSB   80                // smem row stride bytes (40 bf16, conflict-free)
#define TILEA  (128 * LDSB)      // 10240 B  (A: 128 rows)
#define TILEBN (64 * LDSB)       // 5120 B   (B: 64 rows)
#define BUFB   (2 * TILEA + 2 * TILEBN)  // 30720 B
#define SMEM_TOTAL (2 * BUFB)    // 61440 B double-buffered

#define OFF_AHI 0
#define OFF_ALO TILEA
#define OFF_BHI (2 * TILEA)
#define OFF_BLO (2 * TILEA + TILEBN)

__device__ float g_part[SPLITS * B_ * DV_ * D_];  // 16 MB split-S partials
__device__ float g_KVT[B_ * DV_ * D_];            // KV^T [b][v][d]

// ---------------------------------------------------------------------------
__device__ __forceinline__ uint32_t smem_to_u32(const void* p) {
    uint32_t a;
    asm("{ .reg .u64 t; cvta.to.shared.u64 t, %1; cvt.u32.u64 %0, t; }"
        : "=r"(a) : "l"(p));
    return a;
}
__device__ __forceinline__ void ldmx4(uint32_t* r, uint32_t addr) {
    asm volatile("ldmatrix.sync.aligned.m8n8.x4.shared.b16 {%0,%1,%2,%3}, [%4];"
        : "=r"(r[0]), "=r"(r[1]), "=r"(r[2]), "=r"(r[3]) : "r"(addr));
}
__device__ __forceinline__ void mma16816(float* c, const uint32_t* a, const uint32_t* b) {
    asm volatile(
        "mma.sync.aligned.m16n8k16.row.col.f32.bf16.bf16.f32 "
        "{%0,%1,%2,%3}, {%4,%5,%6,%7}, {%8,%9}, {%0,%1,%2,%3};"
        : "+f"(c[0]), "+f"(c[1]), "+f"(c[2]), "+f"(c[3])
        : "r"(a[0]), "r"(a[1]), "r"(a[2]), "r"(a[3]), "r"(b[0]), "r"(b[1]));
}

// float -> (bf16 hi, bf16 lo) packed pairs
__device__ __forceinline__ void split2(float x0, float x1, uint32_t& h, uint32_t& l) {
    __nv_bfloat16 h0 = __float2bfloat16(x0), h1 = __float2bfloat16(x1);
    float r0 = x0 - __bfloat162float(h0), r1 = x1 - __bfloat162float(h1);
    __nv_bfloat16 l0 = __float2bfloat16(r0), l1 = __float2bfloat16(r1);
    h = ((uint32_t)__bfloat16_as_ushort(h1) << 16) | (uint32_t)__bfloat16_as_ushort(h0);
    l = ((uint32_t)__bfloat16_as_ushort(l1) << 16) | (uint32_t)__bfloat16_as_ushort(l0);
}

// One 128x64x32 chunk for this warp (warp tile 32x32).
// acc[mi*4+ni][4]. PRODUCT-MAJOR ordering: three passes (hh, hl, lh),
// each touching all 8 accumulators -> dependent acc reuse distance = 8 MMAs.
__device__ __forceinline__ void warp_chunk_mma(
    uint32_t buf, int lane, int wm, int wn, float (*acc)[4])
{
    const uint32_t aHi = buf + OFF_AHI, aLo = buf + OFF_ALO;
    const uint32_t bHi = buf + OFF_BHI, bLo = buf + OFF_BLO;
#pragma unroll
    for (int ks = 0; ks < 2; ks++) {
        uint32_t aoff = (uint32_t)((wm + (lane & 15)) * LDSB
                                   + ((lane >> 4) * 8 + ks * 16) * 2);
        uint32_t ah[2][4], al[2][4];
#pragma unroll
        for (int mi = 0; mi < 2; mi++) {
            ldmx4(ah[mi], aHi + aoff + mi * 16 * LDSB);
            ldmx4(al[mi], aLo + aoff + mi * 16 * LDSB);
        }
        uint32_t boff = (uint32_t)((wn + (lane & 7) + ((lane >> 4) << 3)) * LDSB
                                   + (((lane >> 3) & 1) * 8 + ks * 16) * 2);
        uint32_t bh[4][2], bl[4][2];
#pragma unroll
        for (int pi = 0; pi < 2; pi++) {
            uint32_t r4[4];
            ldmx4(r4, bHi + boff + pi * 16 * LDSB);
            bh[2*pi][0] = r4[0]; bh[2*pi][1] = r4[1];
            bh[2*pi+1][0] = r4[2]; bh[2*pi+1][1] = r4[3];
            ldmx4(r4, bLo + boff + pi * 16 * LDSB);
            bl[2*pi][0] = r4[0]; bl[2*pi][1] = r4[1];
            bl[2*pi+1][0] = r4[2]; bl[2*pi+1][1] = r4[3];
        }
        // pass 1: hi*hi
#pragma unroll
        for (int mi = 0; mi < 2; mi++)
#pragma unroll
            for (int ni = 0; ni < 4; ni++)
                mma16816(acc[mi * 4 + ni], ah[mi], bh[ni]);
        // pass 2: hi*lo
#pragma unroll
        for (int mi = 0; mi < 2; mi++)
#pragma unroll
            for (int ni = 0; ni < 4; ni++)
                mma16816(acc[mi * 4 + ni], ah[mi], bl[ni]);
        // pass 3: lo*hi
#pragma unroll
        for (int mi = 0; mi < 2; mi++)
#pragma unroll
            for (int ni = 0; ni < 4; ni++)
                mma16816(acc[mi * 4 + ni], al[mi], bh[ni]);
    }
}

// ---------------------------------------------------------------------------
// Kernel 1: partial KV^T[v,d] = sum_{s in split} V[s,v] * (relu(K[s,d])+eps)
// A = V^T (128 v-rows), B = K_^T (64 d-rows). Grid (8, SPLITS, B) = 512 CTAs.
// ---------------------------------------------------------------------------
__global__ __launch_bounds__(256, 2)
void kv_kernel(const float* __restrict__ K, const float* __restrict__ V) {
    extern __shared__ __align__(16) char smem[];
    const uint32_t sb = smem_to_u32(smem);

    const int t = threadIdx.x, lane = t & 31, wid = t >> 5;
    const int wm = (wid & 3) * 32, wn = (wid >> 2) * 32;
    const int b = blockIdx.z, p = blockIdx.y;
    const int v0 = (blockIdx.x & 1) * 128, d0 = (blockIdx.x >> 1) * 64;

    const float* __restrict__ Vb = V + (size_t)b * S_ * DV_;
    const float* __restrict__ Kb = K + (size_t)b * S_ * D_;

    float acc[8][4];
#pragma unroll
    for (int i = 0; i < 8; i++)
#pragma unroll
        for (int j = 0; j < 4; j++) acc[i][j] = 0.0f;

    float ra[16], rb[8];
    const int rA  = t & 127;          // A row (v)
    const int sgA = (t >> 7) * 4;     // A s-group base (4 groups)
    const int rB  = t & 63;           // B row (d)
    const int sgB = (t >> 6) * 2;     // B s-group base (2 groups)

    // prologue: chunk 0
    {
        const int s_c = p * S_PER;
#pragma unroll
        for (int i = 0; i < 4; i++) {
            int s0 = s_c + (sgA + i) * 4;
#pragma unroll
            for (int j = 0; j < 4; j++)
                ra[i * 4 + j] = Vb[(size_t)(s0 + j) * DV_ + v0 + rA];
        }
#pragma unroll
        for (int i = 0; i < 2; i++) {
            int s0 = s_c + (sgB + i) * 4;
#pragma unroll
            for (int j = 0; j < 4; j++)
                rb[i * 4 + j] = fmaxf(Kb[(size_t)(s0 + j) * D_ + d0 + rB], 0.f) + EPS_;
        }
    }

    const int NC = S_PER / KC;   // 16
    for (int c = 0; c < NC; c++) {
        char* base = smem + (size_t)(c & 1) * BUFB;
#pragma unroll
        for (int i = 0; i < 4; i++) {
            int sg = sgA + i;
            uint32_t h01, l01, h23, l23;
            split2(ra[i*4+0], ra[i*4+1], h01, l01);
            split2(ra[i*4+2], ra[i*4+3], h23, l23);
            *(uint2*)(base + OFF_AHI + rA * LDSB + sg * 8) = make_uint2(h01, h23);
            *(uint2*)(base + OFF_ALO + rA * LDSB + sg * 8) = make_uint2(l01, l23);
        }
#pragma unroll
        for (int i = 0; i < 2; i++) {
            int sg = sgB + i;
            uint32_t h01, l01, h23, l23;
            split2(rb[i*4+0], rb[i*4+1], h01, l01);
            split2(rb[i*4+2], rb[i*4+3], h23, l23);
            *(uint2*)(base + OFF_BHI + rB * LDSB + sg * 8) = make_uint2(h01, h23);
            *(uint2*)(base + OFF_BLO + rB * LDSB + sg * 8) = make_uint2(l01, l23);
        }
        __syncthreads();
        if (c + 1 < NC) {
            const int s_c = p * S_PER + (c + 1) * KC;
#pragma unroll
            for (int i = 0; i < 4; i++) {
                int s0 = s_c + (sgA + i) * 4;
#pragma unroll
                for (int j = 0; j < 4; j++)
                    ra[i * 4 + j] = Vb[(size_t)(s0 + j) * DV_ + v0 + rA];
            }
#pragma unroll
            for (int i = 0; i < 2; i++) {
                int s0 = s_c + (sgB + i) * 4;
#pragma unroll
                for (int j = 0; j < 4; j++)
                    rb[i * 4 + j] = fmaxf(Kb[(size_t)(s0 + j) * D_ + d0 + rB], 0.f) + EPS_;
            }
        }
        warp_chunk_mma(sb + (uint32_t)(c & 1) * BUFB, lane, wm, wn, acc);
    }

    // Epilogue: C[v,d] -> g_part
    float* dst = g_part + (size_t)(p * B_ + b) * DV_ * D_;
    const int rr = lane >> 2, cc = (lane & 3) * 2;
#pragma unroll
    for (int mi = 0; mi < 2; mi++)
#pragma unroll
        for (int ni = 0; ni < 4; ni++) {
            int row = v0 + wm + mi * 16 + rr;
            int col = d0 + wn + ni * 8 + cc;
            float* cp = acc[mi * 4 + ni];
            *(float2*)(dst + (size_t)row * D_ + col)       = make_float2(cp[0], cp[1]);
            *(float2*)(dst + (size_t)(row + 8) * D_ + col) = make_float2(cp[2], cp[3]);
        }
}

// ---------------------------------------------------------------------------
// Kernel 2: g_KVT = sum over SPLITS partials
// ---------------------------------------------------------------------------
__global__ __launch_bounds__(256)
void reduce_kernel() {
    const int i = blockIdx.x * 256 + threadIdx.x;  // float4 idx, 131072 total
    const size_t stride4 = (size_t)B_ * DV_ * D_ / 4;
    float4 acc = make_float4(0.f, 0.f, 0.f, 0.f);
#pragma unroll
    for (int p = 0; p < SPLITS; p++) {
        float4 v = ((const float4*)g_part)[p * stride4 + i];
        acc.x += v.x; acc.y += v.y; acc.z += v.z; acc.w += v.w;
    }
    ((float4*)g_KVT)[i] = acc;
}

// ---------------------------------------------------------------------------
// Kernel 3: out[q,v] = (relu(Q)+eps)[q,d] @ KVT[v,d]^T
// A = Q_ (128 q-rows), B = KVT (64 v-rows). Grid (4, 32, B) = 1024 CTAs.
// ---------------------------------------------------------------------------
__global__ __launch_bounds__(256, 2)
void out_kernel(const float* __restrict__ Q, float* __restrict__ O) {
    extern __shared__ __align__(16) char smem[];
    const uint32_t sb = smem_to_u32(smem);

    const int t = threadIdx.x, lane = t & 31, wid = t >> 5;
    const int wm = (wid & 3) * 32, wn = (wid >> 2) * 32;
    const int b = blockIdx.z;
    const int q0 = blockIdx.y * 128, v0 = blockIdx.x * 64;

    const float* __restrict__ Qb = Q + (size_t)b * S_ * D_;
    const float* __restrict__ Cb = g_KVT + (size_t)b * DV_ * D_;

    float acc[8][4];
#pragma unroll
    for (int i = 0; i < 8; i++)
#pragma unroll
        for (int j = 0; j < 4; j++) acc[i][j] = 0.0f;

    float4 rq[4], rc[2];
#pragma unroll
    for (int i = 0; i < 4; i++) {
        int idx = t + i * 256;
        rq[i] = *(const float4*)(Qb + (size_t)(q0 + (idx >> 3)) * D_ + (idx & 7) * 4);
    }
#pragma unroll
    for (int i = 0; i < 2; i++) {
        int idx = t + i * 256;
        rc[i] = *(const float4*)(Cb + (size_t)(v0 + (idx >> 3)) * D_ + (idx & 7) * 4);
    }

    const int NC = D_ / KC;   // 8
    for (int c = 0; c < NC; c++) {
        char* base = smem + (size_t)(c & 1) * BUFB;
#pragma unroll
        for (int i = 0; i < 4; i++) {
            int idx = t + i * 256;
            int row = idx >> 3, f4 = idx & 7;
            float4 q4 = rq[i];
            q4.x = fmaxf(q4.x, 0.f) + EPS_;
            q4.y = fmaxf(q4.y, 0.f) + EPS_;
            q4.z = fmaxf(q4.z, 0.f) + EPS_;
            q4.w = fmaxf(q4.w, 0.f) + EPS_;
            uint32_t h01, l01, h23, l23;
            split2(q4.x, q4.y, h01, l01); split2(q4.z, q4.w, h23, l23);
            *(uint2*)(base + OFF_AHI + row * LDSB + f4 * 8) = make_uint2(h01, h23);
            *(uint2*)(base + OFF_ALO + row * LDSB + f4 * 8) = make_uint2(l01, l23);
        }
#pragma unroll
        for (int i = 0; i < 2; i++) {
            int idx = t + i * 256;
            int row = idx >> 3, f4 = idx & 7;
            uint32_t h01, l01, h23, l23;
            float4 c4 = rc[i];
            split2(c4.x, c4.y, h01, l01); split2(c4.z, c4.w, h23, l23);
            *(uint2*)(base + OFF_BHI + row * LDSB + f4 * 8) = make_uint2(h01, h23);
            *(uint2*)(base + OFF_BLO + row * LDSB + f4 * 8) = make_uint2(l01, l23);
        }
        __syncthreads();
        if (c + 1 < NC) {
            const int dc = (c + 1) * KC;
#pragma unroll
            for (int i = 0; i < 4; i++) {
                int idx = t + i * 256;
                rq[i] = *(const float4*)(Qb + (size_t)(q0 + (idx >> 3)) * D_ + dc + (idx & 7) * 4);
            }
#pragma unroll
            for (int i = 0; i < 2; i++) {
                int idx = t + i * 256;
                rc[i] = *(const float4*)(Cb + (size_t)(v0 + (idx >> 3)) * D_ + dc + (idx & 7) * 4);
            }
        }
        warp_chunk_mma(sb + (uint32_t)(c & 1) * BUFB, lane, wm, wn, acc);
    }

    // Epilogue: C[q,v] -> O
    float* dst = O + (size_t)b * S_ * DV_;
    const int rr = lane >> 2, cc = (lane & 3) * 2;
#pragma unroll
    for (int mi = 0; mi < 2; mi++)
#pragma unroll
        for (int ni = 0; ni < 4; ni++) {
            int row = q0 + wm + mi * 16 + rr;
            int col = v0 + wn + ni * 8 + cc;
            float* cp = acc[mi * 4 + ni];
            *(float2*)(dst + (size_t)row * DV_ + col)       = make_float2(cp[0], cp[1]);
            *(float2*)(dst + (size_t)(row + 8) * DV_ + col) = make_float2(cp[2], cp[3]);
        }
}

extern "C" void kernel_launch(void* const* d_in, const int* in_sizes, int n_in,
                              void* d_out, int out_size) {
    const float* Q = (const float*)d_in[0];
    const float* K = (const float*)d_in[1];
    const float* V = (const float*)d_in[2];
    float* O = (float*)d_out;

    cudaFuncSetAttribute(kv_kernel,  cudaFuncAttributeMaxDynamicSharedMemorySize, SMEM_TOTAL);
    cudaFuncSetAttribute(out_kernel, cudaFuncAttributeMaxDynamicSharedMemorySize, SMEM_TOTAL);

    kv_kernel<<<dim3(8, SPLITS, B_), 256, SMEM_TOTAL>>>(K, V);
    reduce_kernel<<<512, 256>>>();
    out_kernel<<<dim3(4, 32, B_), 256, SMEM_TOTAL>>>(Q, O);
}

// round 7
// speedup vs baseline: 3.4616x; 1.2744x over previous
#include <cuda_runtime.h>
#include <cuda_bf16.h>
#include <cstdint>

#define B_  8
#define S_  4096
#define D_  256
#define DV_ 256
#define EPS_ 1e-6f

#define SPLITS 8
#define S_PER  (S_ / SPLITS)     // 512
#define KC     32                // k-chunk (bf16 elems)

// ---------------- kv_kernel smem layout: [k][m] / [k][n] tiles -------------
#define LDA_KV 272               // 128 bf16 = 256B + 16 pad (= 4 words mod 32)
#define LDB_KV 144               // 64 bf16 = 128B + 16 pad
#define A_TILE_KV (KC * LDA_KV)  // 8704
#define B_TILE_KV (KC * LDB_KV)  // 4608
#define OFFK_AHI 0
#define OFFK_ALO A_TILE_KV
#define OFFK_BHI (2 * A_TILE_KV)
#define OFFK_BLO (2 * A_TILE_KV + B_TILE_KV)
#define BUF_KV   (2 * A_TILE_KV + 2 * B_TILE_KV)   // 26624
#define SMEM_KV  (2 * BUF_KV)                      // 53248

// ---------------- out_kernel smem layout: [row][k] tiles (proven) ----------
#define LDSB   80
#define TILEA  (128 * LDSB)
#define TILEBN (64 * LDSB)
#define OFF_AHI 0
#define OFF_ALO TILEA
#define OFF_BHI (2 * TILEA)
#define OFF_BLO (2 * TILEA + TILEBN)
#define BUF_OUT (2 * TILEA + 2 * TILEBN)           // 30720
#define SMEM_OUT (2 * BUF_OUT)                     // 61440

__device__ float g_part[SPLITS * B_ * DV_ * D_];  // 16 MB split-S partials
__device__ float g_KVT[B_ * DV_ * D_];            // KV^T [b][v][d]

// ---------------------------------------------------------------------------
__device__ __forceinline__ uint32_t smem_to_u32(const void* p) {
    uint32_t a;
    asm("{ .reg .u64 t; cvta.to.shared.u64 t, %1; cvt.u32.u64 %0, t; }"
        : "=r"(a) : "l"(p));
    return a;
}
__device__ __forceinline__ void ldmx4(uint32_t* r, uint32_t addr) {
    asm volatile("ldmatrix.sync.aligned.m8n8.x4.shared.b16 {%0,%1,%2,%3}, [%4];"
        : "=r"(r[0]), "=r"(r[1]), "=r"(r[2]), "=r"(r[3]) : "r"(addr));
}
__device__ __forceinline__ void ldmx4t(uint32_t* r, uint32_t addr) {
    asm volatile("ldmatrix.sync.aligned.m8n8.x4.trans.shared.b16 {%0,%1,%2,%3}, [%4];"
        : "=r"(r[0]), "=r"(r[1]), "=r"(r[2]), "=r"(r[3]) : "r"(addr));
}
__device__ __forceinline__ void mma16816(float* c, const uint32_t* a, const uint32_t* b) {
    asm volatile(
        "mma.sync.aligned.m16n8k16.row.col.f32.bf16.bf16.f32 "
        "{%0,%1,%2,%3}, {%4,%5,%6,%7}, {%8,%9}, {%0,%1,%2,%3};"
        : "+f"(c[0]), "+f"(c[1]), "+f"(c[2]), "+f"(c[3])
        : "r"(a[0]), "r"(a[1]), "r"(a[2]), "r"(a[3]), "r"(b[0]), "r"(b[1]));
}

// Cheap truncation split: hi = top-16-bits(x) (exact bf16), lo = rn_bf16(x-hi).
// x - hi is exact in fp32 (same exponent, mantissa subtraction).
__device__ __forceinline__ void split2f(float x0, float x1, uint32_t& h, uint32_t& l) {
    uint32_t u0 = __float_as_uint(x0), u1 = __float_as_uint(x1);
    asm("prmt.b32 %0, %1, %2, 0x7632;" : "=r"(h) : "r"(u0), "r"(u1));
    float r0 = x0 - __uint_as_float(u0 & 0xFFFF0000u);
    float r1 = x1 - __uint_as_float(u1 & 0xFFFF0000u);
    asm("cvt.rn.bf16x2.f32 %0, %1, %2;" : "=r"(l) : "f"(r1), "f"(r0));
}

// ---------------------------------------------------------------------------
// kv MMA chunk: tiles stored [k][col] (k rows). A/B fragments via ldmatrix.trans.
// A: k x 128 (m=v), stride LDA_KV.  B: k x 64 (n=d), stride LDB_KV.
// acc[mi*4+ni][4], warp tile 32(m) x 32(n).
// ---------------------------------------------------------------------------
__device__ __forceinline__ void warp_chunk_mma_kv(
    uint32_t buf, int lane, int wm, int wn, float (*acc)[4])
{
    const uint32_t aHi = buf + OFFK_AHI, aLo = buf + OFFK_ALO;
    const uint32_t bHi = buf + OFFK_BHI, bLo = buf + OFFK_BLO;
#pragma unroll
    for (int ks = 0; ks < 2; ks++) {
        // A (trans): block j gets lanes 8j..8j+7.
        // blocks: (m0-7,k0-7),(m8-15,k0-7),(m0-7,k8-15),(m8-15,k8-15)
        // lane -> stored row k, col m:
        int krA = ks * 16 + (lane & 7) + ((lane >> 4) & 1) * 8;
        int mcA = wm + ((lane >> 3) & 1) * 8;
        uint32_t aoff = (uint32_t)(krA * LDA_KV + mcA * 2);
        uint32_t ah[2][4], al[2][4];
#pragma unroll
        for (int mi = 0; mi < 2; mi++) {
            ldmx4t(ah[mi], aHi + aoff + mi * 32);   // +16 m-cols = 32B
            ldmx4t(al[mi], aLo + aoff + mi * 32);
        }
        // B (trans): blocks (k0-7,n0-7),(k8-15,n0-7),(k0-7,n8-15),(k8-15,n8-15)
        int krB = ks * 16 + (lane & 7) + ((lane >> 3) & 1) * 8;
        int ncB = wn + (lane >> 4) * 8;
        uint32_t boff = (uint32_t)(krB * LDB_KV + ncB * 2);
        uint32_t bh[4][2], bl[4][2];
#pragma unroll
        for (int pi = 0; pi < 2; pi++) {
            uint32_t r4[4];
            ldmx4t(r4, bHi + boff + pi * 32);       // +16 n-cols = 32B
            bh[2*pi][0] = r4[0]; bh[2*pi][1] = r4[1];
            bh[2*pi+1][0] = r4[2]; bh[2*pi+1][1] = r4[3];
            ldmx4t(r4, bLo + boff + pi * 32);
            bl[2*pi][0] = r4[0]; bl[2*pi][1] = r4[1];
            bl[2*pi+1][0] = r4[2]; bl[2*pi+1][1] = r4[3];
        }
#pragma unroll
        for (int mi = 0; mi < 2; mi++)
#pragma unroll
            for (int ni = 0; ni < 4; ni++)
                mma16816(acc[mi * 4 + ni], ah[mi], bh[ni]);
#pragma unroll
        for (int mi = 0; mi < 2; mi++)
#pragma unroll
            for (int ni = 0; ni < 4; ni++)
                mma16816(acc[mi * 4 + ni], ah[mi], bl[ni]);
#pragma unroll
        for (int mi = 0; mi < 2; mi++)
#pragma unroll
            for (int ni = 0; ni < 4; ni++)
                mma16816(acc[mi * 4 + ni], al[mi], bh[ni]);
    }
}

// out MMA chunk: tiles [row][k], stride LDSB (proven round-5 path).
__device__ __forceinline__ void warp_chunk_mma_out(
    uint32_t buf, int lane, int wm, int wn, float (*acc)[4])
{
    const uint32_t aHi = buf + OFF_AHI, aLo = buf + OFF_ALO;
    const uint32_t bHi = buf + OFF_BHI, bLo = buf + OFF_BLO;
#pragma unroll
    for (int ks = 0; ks < 2; ks++) {
        uint32_t aoff = (uint32_t)((wm + (lane & 15)) * LDSB
                                   + ((lane >> 4) * 8 + ks * 16) * 2);
        uint32_t ah[2][4], al[2][4];
#pragma unroll
        for (int mi = 0; mi < 2; mi++) {
            ldmx4(ah[mi], aHi + aoff + mi * 16 * LDSB);
            ldmx4(al[mi], aLo + aoff + mi * 16 * LDSB);
        }
        uint32_t boff = (uint32_t)((wn + (lane & 7) + ((lane >> 4) << 3)) * LDSB
                                   + (((lane >> 3) & 1) * 8 + ks * 16) * 2);
        uint32_t bh[4][2], bl[4][2];
#pragma unroll
        for (int pi = 0; pi < 2; pi++) {
            uint32_t r4[4];
            ldmx4(r4, bHi + boff + pi * 16 * LDSB);
            bh[2*pi][0] = r4[0]; bh[2*pi][1] = r4[1];
            bh[2*pi+1][0] = r4[2]; bh[2*pi+1][1] = r4[3];
            ldmx4(r4, bLo + boff + pi * 16 * LDSB);
            bl[2*pi][0] = r4[0]; bl[2*pi][1] = r4[1];
            bl[2*pi+1][0] = r4[2]; bl[2*pi+1][1] = r4[3];
        }
#pragma unroll
        for (int mi = 0; mi < 2; mi++)
#pragma unroll
            for (int ni = 0; ni < 4; ni++)
                mma16816(acc[mi * 4 + ni], ah[mi], bh[ni]);
#pragma unroll
        for (int mi = 0; mi < 2; mi++)
#pragma unroll
            for (int ni = 0; ni < 4; ni++)
                mma16816(acc[mi * 4 + ni], ah[mi], bl[ni]);
#pragma unroll
        for (int mi = 0; mi < 2; mi++)
#pragma unroll
            for (int ni = 0; ni < 4; ni++)
                mma16816(acc[mi * 4 + ni], al[mi], bh[ni]);
    }
}

// ---------------------------------------------------------------------------
// Kernel 1: partial KV^T[v,d] = sum_{s in split} V[s,v] * (relu(K[s,d])+eps)
// Natural coalesced float4 loads; tiles stored k-major; ldmatrix.trans MMA.
// Grid (8, SPLITS, B) = 512 CTAs.
// ---------------------------------------------------------------------------
__global__ __launch_bounds__(256, 2)
void kv_kernel(const float* __restrict__ K, const float* __restrict__ V) {
    extern __shared__ __align__(16) char smem[];
    const uint32_t sb = smem_to_u32(smem);

    const int t = threadIdx.x, lane = t & 31, wid = t >> 5;
    const int wm = (wid & 3) * 32, wn = (wid >> 2) * 32;
    const int b = blockIdx.z, p = blockIdx.y;
    const int v0 = (blockIdx.x & 1) * 128, d0 = (blockIdx.x >> 1) * 64;

    const float* __restrict__ Vb = V + (size_t)b * S_ * DV_;
    const float* __restrict__ Kb = K + (size_t)b * S_ * D_;

    float acc[8][4];
#pragma unroll
    for (int i = 0; i < 8; i++)
#pragma unroll
        for (int j = 0; j < 4; j++) acc[i][j] = 0.0f;

    // A slots: idx = t + i*256 (i<4): sA = idx>>5, v4 = idx&31
    // B slots: idx = t + i*256 (i<2): sB = idx>>4, d4 = idx&15
    float4 ra[4], rb[2];
    {
        const int s_c = p * S_PER;
#pragma unroll
        for (int i = 0; i < 4; i++) {
            int idx = t + i * 256;
            ra[i] = *(const float4*)(Vb + (size_t)(s_c + (idx >> 5)) * DV_ + v0 + (idx & 31) * 4);
        }
#pragma unroll
        for (int i = 0; i < 2; i++) {
            int idx = t + i * 256;
            rb[i] = *(const float4*)(Kb + (size_t)(s_c + (idx >> 4)) * D_ + d0 + (idx & 15) * 4);
        }
    }

    const int NC = S_PER / KC;   // 16
    for (int c = 0; c < NC; c++) {
        char* base = smem + (size_t)(c & 1) * BUF_KV;
#pragma unroll
        for (int i = 0; i < 4; i++) {
            int idx = t + i * 256;
            int s = idx >> 5, v4 = idx & 31;
            uint32_t h01, l01, h23, l23;
            split2f(ra[i].x, ra[i].y, h01, l01);
            split2f(ra[i].z, ra[i].w, h23, l23);
            *(uint2*)(base + OFFK_AHI + s * LDA_KV + v4 * 8) = make_uint2(h01, h23);
            *(uint2*)(base + OFFK_ALO + s * LDA_KV + v4 * 8) = make_uint2(l01, l23);
        }
#pragma unroll
        for (int i = 0; i < 2; i++) {
            int idx = t + i * 256;
            int s = idx >> 4, d4 = idx & 15;
            float b0 = fmaxf(rb[i].x, 0.f) + EPS_;
            float b1 = fmaxf(rb[i].y, 0.f) + EPS_;
            float b2 = fmaxf(rb[i].z, 0.f) + EPS_;
            float b3 = fmaxf(rb[i].w, 0.f) + EPS_;
            uint32_t h01, l01, h23, l23;
            split2f(b0, b1, h01, l01);
            split2f(b2, b3, h23, l23);
            *(uint2*)(base + OFFK_BHI + s * LDB_KV + d4 * 8) = make_uint2(h01, h23);
            *(uint2*)(base + OFFK_BLO + s * LDB_KV + d4 * 8) = make_uint2(l01, l23);
        }
        __syncthreads();
        if (c + 1 < NC) {
            const int s_c = p * S_PER + (c + 1) * KC;
#pragma unroll
            for (int i = 0; i < 4; i++) {
                int idx = t + i * 256;
                ra[i] = *(const float4*)(Vb + (size_t)(s_c + (idx >> 5)) * DV_ + v0 + (idx & 31) * 4);
            }
#pragma unroll
            for (int i = 0; i < 2; i++) {
                int idx = t + i * 256;
                rb[i] = *(const float4*)(Kb + (size_t)(s_c + (idx >> 4)) * D_ + d0 + (idx & 15) * 4);
            }
        }
        warp_chunk_mma_kv(sb + (uint32_t)(c & 1) * BUF_KV, lane, wm, wn, acc);
    }

    // Epilogue: C[v,d] -> g_part
    float* dst = g_part + (size_t)(p * B_ + b) * DV_ * D_;
    const int rr = lane >> 2, cc = (lane & 3) * 2;
#pragma unroll
    for (int mi = 0; mi < 2; mi++)
#pragma unroll
        for (int ni = 0; ni < 4; ni++) {
            int row = v0 + wm + mi * 16 + rr;
            int col = d0 + wn + ni * 8 + cc;
            float* cp = acc[mi * 4 + ni];
            *(float2*)(dst + (size_t)row * D_ + col)       = make_float2(cp[0], cp[1]);
            *(float2*)(dst + (size_t)(row + 8) * D_ + col) = make_float2(cp[2], cp[3]);
        }
}

// ---------------------------------------------------------------------------
// Kernel 2: g_KVT = sum over SPLITS partials
// ---------------------------------------------------------------------------
__global__ __launch_bounds__(256)
void reduce_kernel() {
    const int i = blockIdx.x * 256 + threadIdx.x;  // float4 idx, 131072 total
    const size_t stride4 = (size_t)B_ * DV_ * D_ / 4;
    float4 acc = make_float4(0.f, 0.f, 0.f, 0.f);
#pragma unroll
    for (int p = 0; p < SPLITS; p++) {
        float4 v = ((const float4*)g_part)[p * stride4 + i];
        acc.x += v.x; acc.y += v.y; acc.z += v.z; acc.w += v.w;
    }
    ((float4*)g_KVT)[i] = acc;
}

// ---------------------------------------------------------------------------
// Kernel 3: out[q,v] = (relu(Q)+eps)[q,d] @ KVT[v,d]^T
// Grid (4, 32, B) = 1024 CTAs.
// ---------------------------------------------------------------------------
__global__ __launch_bounds__(256, 2)
void out_kernel(const float* __restrict__ Q, float* __restrict__ O) {
    extern __shared__ __align__(16) char smem[];
    const uint32_t sb = smem_to_u32(smem);

    const int t = threadIdx.x, lane = t & 31, wid = t >> 5;
    const int wm = (wid & 3) * 32, wn = (wid >> 2) * 32;
    const int b = blockIdx.z;
    const int q0 = blockIdx.y * 128, v0 = blockIdx.x * 64;

    const float* __restrict__ Qb = Q + (size_t)b * S_ * D_;
    const float* __restrict__ Cb = g_KVT + (size_t)b * DV_ * D_;

    float acc[8][4];
#pragma unroll
    for (int i = 0; i < 8; i++)
#pragma unroll
        for (int j = 0; j < 4; j++) acc[i][j] = 0.0f;

    float4 rq[4], rc[2];
#pragma unroll
    for (int i = 0; i < 4; i++) {
        int idx = t + i * 256;
        rq[i] = *(const float4*)(Qb + (size_t)(q0 + (idx >> 3)) * D_ + (idx & 7) * 4);
    }
#pragma unroll
    for (int i = 0; i < 2; i++) {
        int idx = t + i * 256;
        rc[i] = *(const float4*)(Cb + (size_t)(v0 + (idx >> 3)) * D_ + (idx & 7) * 4);
    }

    const int NC = D_ / KC;   // 8
    for (int c = 0; c < NC; c++) {
        char* base = smem + (size_t)(c & 1) * BUF_OUT;
#pragma unroll
        for (int i = 0; i < 4; i++) {
            int idx = t + i * 256;
            int row = idx >> 3, f4 = idx & 7;
            float q0f = fmaxf(rq[i].x, 0.f) + EPS_;
            float q1f = fmaxf(rq[i].y, 0.f) + EPS_;
            float q2f = fmaxf(rq[i].z, 0.f) + EPS_;
            float q3f = fmaxf(rq[i].w, 0.f) + EPS_;
            uint32_t h01, l01, h23, l23;
            split2f(q0f, q1f, h01, l01); split2f(q2f, q3f, h23, l23);
            *(uint2*)(base + OFF_AHI + row * LDSB + f4 * 8) = make_uint2(h01, h23);
            *(uint2*)(base + OFF_ALO + row * LDSB + f4 * 8) = make_uint2(l01, l23);
        }
#pragma unroll
        for (int i = 0; i < 2; i++) {
            int idx = t + i * 256;
            int row = idx >> 3, f4 = idx & 7;
            uint32_t h01, l01, h23, l23;
            split2f(rc[i].x, rc[i].y, h01, l01); split2f(rc[i].z, rc[i].w, h23, l23);
            *(uint2*)(base + OFF_BHI + row * LDSB + f4 * 8) = make_uint2(h01, h23);
            *(uint2*)(base + OFF_BLO + row * LDSB + f4 * 8) = make_uint2(l01, l23);
        }
        __syncthreads();
        if (c + 1 < NC) {
            const int dc = (c + 1) * KC;
#pragma unroll
            for (int i = 0; i < 4; i++) {
                int idx = t + i * 256;
                rq[i] = *(const float4*)(Qb + (size_t)(q0 + (idx >> 3)) * D_ + dc + (idx & 7) * 4);
            }
#pragma unroll
            for (int i = 0; i < 2; i++) {
                int idx = t + i * 256;
                rc[i] = *(const float4*)(Cb + (size_t)(v0 + (idx >> 3)) * D_ + dc + (idx & 7) * 4);
            }
        }
        warp_chunk_mma_out(sb + (uint32_t)(c & 1) * BUF_OUT, lane, wm, wn, acc);
    }

    // Epilogue: C[q,v] -> O
    float* dst = O + (size_t)b * S_ * DV_;
    const int rr = lane >> 2, cc = (lane & 3) * 2;
#pragma unroll
    for (int mi = 0; mi < 2; mi++)
#pragma unroll
        for (int ni = 0; ni < 4; ni++) {
            int row = q0 + wm + mi * 16 + rr;
            int col = v0 + wn + ni * 8 + cc;
            float* cp = acc[mi * 4 + ni];
            *(float2*)(dst + (size_t)row * DV_ + col)       = make_float2(cp[0], cp[1]);
            *(float2*)(dst + (size_t)(row + 8) * DV_ + col) = make_float2(cp[2], cp[3]);
        }
}

extern "C" void kernel_launch(void* const* d_in, const int* in_sizes, int n_in,
                              void* d_out, int out_size) {
    const float* Q = (const float*)d_in[0];
    const float* K = (const float*)d_in[1];
    const float* V = (const float*)d_in[2];
    float* O = (float*)d_out;

    cudaFuncSetAttribute(kv_kernel,  cudaFuncAttributeMaxDynamicSharedMemorySize, SMEM_KV);
    cudaFuncSetAttribute(out_kernel, cudaFuncAttributeMaxDynamicSharedMemorySize, SMEM_OUT);

    kv_kernel<<<dim3(8, SPLITS, B_), 256, SMEM_KV>>>(K, V);
    reduce_kernel<<<512, 256>>>();
    out_kernel<<<dim3(4, 32, B_), 256, SMEM_OUT>>>(Q, O);
}